// round 2
// baseline (speedup 1.0000x reference)
#include <cuda_runtime.h>
#include <cuda_bf16.h>
#include <math.h>

#define NN 30000
#define EE 480000
#define DD 128
#define CAP 96          // padded CSR capacity per node (Poisson(16): P(deg>96) ~ 1e-40)

// ---------------- static device scratch ----------------
__device__ float g_z[NN * DD];          // z = h @ W^T
__device__ float g_hout[NN * DD];       // aggregated output pre-BN
__device__ int   g_cursor[NN];          // per-node in-degree counter
__device__ int   g_srcs[NN * CAP];      // padded CSR: srcs of incoming edges
__device__ float g_stats[2 * DD];       // [0:128) sum, [128:256) sumsq

// ---------------- fma.rn.f32x2 (packed dual-FMA, FMA pipe 2x) ----------------
__device__ __forceinline__ void fma2(unsigned long long& d,
                                     unsigned long long a,
                                     unsigned long long b) {
    asm("fma.rn.f32x2 %0, %1, %2, %0;" : "+l"(d) : "l"(a), "l"(b));
}

// ---------------- zero init ----------------
__global__ void zero_kernel() {
    int i = blockIdx.x * 256 + threadIdx.x;
    if (i < NN) g_cursor[i] = 0;
    if (i < 2 * DD) g_stats[i] = 0.f;
}

// ---------------- GEMM: z[n][o] = sum_k h[n][k] * W[o][k] ----------------
// block: 256 threads -> 64 rows x 128 cols, f32x2 packed FMA
__global__ void gemm_kernel(const float* __restrict__ h, const float* __restrict__ W) {
    __shared__ float2 As[32][65];     // [kk][row], value duplicated (a,a)
    __shared__ float  Bs[32][130];    // [kk][col], col-major pairs contiguous
    int t = threadIdx.x;
    int tx = t & 31;                  // owns cols {2tx,2tx+1, 64+2tx,64+2tx+1}
    int ty = t >> 5;                  // row group 0..7
    int rowBase = blockIdx.x * 64;

    unsigned long long acc[8][2];
#pragma unroll
    for (int i = 0; i < 8; i++) { acc[i][0] = 0ull; acc[i][1] = 0ull; }

    for (int kc = 0; kc < DD; kc += 32) {
#pragma unroll
        for (int l = 0; l < 8; l++) {            // 64 rows x 32 kk
            int lin = t + 256 * l;
            int r = lin >> 5, kk = lin & 31;
            int row = rowBase + r;
            float v = (row < NN) ? h[row * DD + kc + kk] : 0.f;
            As[kk][r] = make_float2(v, v);
        }
#pragma unroll
        for (int l = 0; l < 16; l++) {           // 128 cols x 32 kk
            int lin = t + 256 * l;
            int c = lin >> 5, kk = lin & 31;
            Bs[kk][c] = W[c * DD + kc + kk];
        }
        __syncthreads();
#pragma unroll
        for (int kk = 0; kk < 32; kk++) {
            unsigned long long b0 = *(const unsigned long long*)&Bs[kk][2 * tx];
            unsigned long long b1 = *(const unsigned long long*)&Bs[kk][64 + 2 * tx];
#pragma unroll
            for (int i = 0; i < 8; i++) {
                unsigned long long a = *(const unsigned long long*)&As[kk][ty + 8 * i];
                fma2(acc[i][0], a, b0);
                fma2(acc[i][1], a, b1);
            }
        }
        __syncthreads();
    }
#pragma unroll
    for (int i = 0; i < 8; i++) {
        int row = rowBase + ty + 8 * i;
        if (row < NN) {
            *(float2*)&g_z[row * DD + 2 * tx]      = *(float2*)&acc[i][0];
            *(float2*)&g_z[row * DD + 64 + 2 * tx] = *(float2*)&acc[i][1];
        }
    }
}

// ---------------- build padded CSR ----------------
__global__ void build_kernel(const int* __restrict__ src, const int* __restrict__ dst) {
    int e = blockIdx.x * 256 + threadIdx.x;
    if (e < EE) {
        int d = dst[e];
        int pos = atomicAdd(&g_cursor[d], 1);
        if (pos < CAP) g_srcs[d * CAP + pos] = src[e];
    }
}

// ---------------- per-dst softmax aggregation (one block per node) ----------------
__global__ void agg_kernel(const float* __restrict__ snorm) {
    int d = blockIdx.x;
    int c = threadIdx.x;              // channel 0..127
    int deg = g_cursor[d];
    if (deg > CAP) deg = CAP;
    __shared__ int ssrc[CAP];
    if (c < deg) ssrc[c] = g_srcs[d * CAP + c];
    float zd = g_z[d * DD + c];
    __syncthreads();

    float den0 = 0.f, acc0 = 0.f, den1 = 0.f, acc1 = 0.f;
    int i = 0;
    for (; i + 2 <= deg; i += 2) {
        float zs0 = g_z[ssrc[i] * DD + c];
        float zs1 = g_z[ssrc[i + 1] * DD + c];
        float w0 = __expf(zs0 * zd);
        float w1 = __expf(zs1 * zd);
        den0 += w0;            acc0 = fmaf(w0, zs0, acc0);
        den1 += w1;            acc1 = fmaf(w1, zs1, acc1);
    }
    if (i < deg) {
        float zs = g_z[ssrc[i] * DD + c];
        float w = __expf(zs * zd);
        den0 += w;             acc0 = fmaf(w, zs, acc0);
    }
    float den = den0 + den1, acc = acc0 + acc1;
    float hv = (den > 0.f) ? (acc / den) * snorm[d] : 0.f;
    g_hout[d * DD + c] = hv;
}

// ---------------- BN statistics (per-channel sum / sumsq) ----------------
__global__ void bnstats_kernel() {
    int c = threadIdx.x;              // 128 threads
    float s = 0.f, s2 = 0.f;
    for (int r = blockIdx.x; r < NN; r += gridDim.x) {
        float v = g_hout[r * DD + c];
        s += v;
        s2 = fmaf(v, v, s2);
    }
    atomicAdd(&g_stats[c], s);
    atomicAdd(&g_stats[DD + c], s2);
}

// ---------------- BN apply + ELU (float4 vectorized) ----------------
__global__ void apply_kernel(const float* __restrict__ gamma,
                             const float* __restrict__ beta,
                             float* __restrict__ out) {
    int q = blockIdx.x * 256 + threadIdx.x;        // float4 index
    if (q >= NN * DD / 4) return;
    int c4 = (q & 31) * 4;                         // channel of lane 0 of the quad
    const float invN = 1.f / (float)NN;
    float4 hv = *(const float4*)&g_hout[q * 4];
    float4 o;
    {
        float mu = g_stats[c4 + 0] * invN;
        float var = g_stats[DD + c4 + 0] * invN - mu * mu;
        float v = (hv.x - mu) * rsqrtf(var + 1e-5f) * gamma[c4 + 0] + beta[c4 + 0];
        o.x = (v > 0.f) ? v : expm1f(v);
    }
    {
        float mu = g_stats[c4 + 1] * invN;
        float var = g_stats[DD + c4 + 1] * invN - mu * mu;
        float v = (hv.y - mu) * rsqrtf(var + 1e-5f) * gamma[c4 + 1] + beta[c4 + 1];
        o.y = (v > 0.f) ? v : expm1f(v);
    }
    {
        float mu = g_stats[c4 + 2] * invN;
        float var = g_stats[DD + c4 + 2] * invN - mu * mu;
        float v = (hv.z - mu) * rsqrtf(var + 1e-5f) * gamma[c4 + 2] + beta[c4 + 2];
        o.z = (v > 0.f) ? v : expm1f(v);
    }
    {
        float mu = g_stats[c4 + 3] * invN;
        float var = g_stats[DD + c4 + 3] * invN - mu * mu;
        float v = (hv.w - mu) * rsqrtf(var + 1e-5f) * gamma[c4 + 3] + beta[c4 + 3];
        o.w = (v > 0.f) ? v : expm1f(v);
    }
    *(float4*)&out[q * 4] = o;
}

// ---------------- launch ----------------
extern "C" void kernel_launch(void* const* d_in, const int* in_sizes, int n_in,
                              void* d_out, int out_size) {
    const float* h      = (const float*)d_in[0];   // [N,128]
    const float* snorm  = (const float*)d_in[1];   // [N,1]
    const float* W      = (const float*)d_in[2];   // [128,128]
    const float* gamma  = (const float*)d_in[3];   // [128]
    const float* beta   = (const float*)d_in[4];   // [128]
    const int*   src    = (const int*)d_in[5];     // [E]
    const int*   dst    = (const int*)d_in[6];     // [E]
    float* out = (float*)d_out;

    zero_kernel<<<(NN + 255) / 256, 256>>>();
    gemm_kernel<<<(NN + 63) / 64, 256>>>(h, W);
    build_kernel<<<(EE + 255) / 256, 256>>>(src, dst);
    agg_kernel<<<NN, 128>>>(snorm);
    bnstats_kernel<<<256, 128>>>();
    apply_kernel<<<(NN * DD / 4 + 255) / 256, 256>>>(gamma, beta, out);
}

// round 3
// speedup vs baseline: 1.8409x; 1.8409x over previous
#include <cuda_runtime.h>
#include <cuda_bf16.h>
#include <math.h>

#define NN 30000
#define EE 480000
#define DD 128
#define CAP 96          // padded CSR capacity (Poisson(16): P(deg>96) ~ 1e-40)
#define WPB 8           // warps (=nodes) per agg block; 30000/8 = 3750 exact

// ---------------- static device scratch ----------------
__device__ float g_z[NN * DD];          // z = h @ W^T
__device__ float g_hout[NN * DD];       // aggregated output pre-BN
__device__ int   g_cursor[NN];          // per-node in-degree counter
__device__ int   g_srcs[NN * CAP];      // padded CSR
__device__ float g_stats[2 * DD];       // sum / sumsq per channel
__device__ float g_scale[DD];           // folded BN scale
__device__ float g_bias[DD];            // folded BN bias

__device__ __forceinline__ float ex2(float x) {
    float r; asm("ex2.approx.f32 %0, %1;" : "=f"(r) : "f"(x)); return r;
}

// ---------------- zero init ----------------
__global__ void zero_kernel() {
    int i = blockIdx.x * 256 + threadIdx.x;
    if (i < NN) g_cursor[i] = 0;
    if (i < 2 * DD) g_stats[i] = 0.f;
}

// ---------------- GEMM (round-1 layout: 64 rows x 128 cols per block) ----------------
__global__ void gemm_kernel(const float* __restrict__ h, const float* __restrict__ W) {
    __shared__ float As[64][33];
    __shared__ float Bs[128][33];
    int t = threadIdx.x;
    int tx = t & 31;
    int ty = t >> 5;
    int rowBase = blockIdx.x * 64;

    float acc[8][4];
#pragma unroll
    for (int i = 0; i < 8; i++)
#pragma unroll
        for (int j = 0; j < 4; j++) acc[i][j] = 0.f;

    for (int kc = 0; kc < DD; kc += 32) {
#pragma unroll
        for (int l = 0; l < 8; l++) {
            int lin = t + 256 * l;
            int r = lin >> 5, kk = lin & 31;
            int row = rowBase + r;
            As[r][kk] = (row < NN) ? h[row * DD + kc + kk] : 0.f;
        }
#pragma unroll
        for (int l = 0; l < 16; l++) {
            int lin = t + 256 * l;
            int r = lin >> 5, kk = lin & 31;
            Bs[r][kk] = W[r * DD + kc + kk];
        }
        __syncthreads();
#pragma unroll
        for (int kk = 0; kk < 32; kk++) {
            float a[8], b[4];
#pragma unroll
            for (int i = 0; i < 8; i++) a[i] = As[ty + 8 * i][kk];
#pragma unroll
            for (int j = 0; j < 4; j++) b[j] = Bs[tx + 32 * j][kk];
#pragma unroll
            for (int i = 0; i < 8; i++)
#pragma unroll
                for (int j = 0; j < 4; j++) acc[i][j] = fmaf(a[i], b[j], acc[i][j]);
        }
        __syncthreads();
    }
#pragma unroll
    for (int i = 0; i < 8; i++) {
        int row = rowBase + ty + 8 * i;
        if (row < NN) {
#pragma unroll
            for (int j = 0; j < 4; j++) g_z[row * DD + tx + 32 * j] = acc[i][j];
        }
    }
}

// ---------------- build padded CSR ----------------
__global__ void build_kernel(const int* __restrict__ src, const int* __restrict__ dst) {
    int e = blockIdx.x * 256 + threadIdx.x;
    if (e < EE) {
        int d = dst[e];
        int pos = atomicAdd(&g_cursor[d], 1);
        if (pos < CAP) g_srcs[d * CAP + pos] = src[e];
    }
}

// ---------------- agg: warp-per-node, float4 channels, fused BN stats ----------------
__global__ void __launch_bounds__(32 * WPB) agg_kernel(const float* __restrict__ snorm) {
    __shared__ int   ssrc[WPB][CAP];
    __shared__ float shv[WPB][DD];       // staged hout rows for BN reduce

    int w = threadIdx.x >> 5;
    int lane = threadIdx.x & 31;
    int d = blockIdx.x * WPB + w;        // grid is exactly NN/WPB

    int deg = g_cursor[d];
    if (deg > CAP) deg = CAP;

    for (int i = lane; i < deg; i += 32) ssrc[w][i] = g_srcs[d * CAP + i];

    const float L2E = 1.44269504f;
    float4 zd = *(const float4*)(g_z + d * DD + lane * 4);
    float4 ze;                           // zd * log2(e), folded once
    ze.x = zd.x * L2E; ze.y = zd.y * L2E; ze.z = zd.z * L2E; ze.w = zd.w * L2E;
    __syncwarp();

    float4 den = make_float4(0.f, 0.f, 0.f, 0.f);
    float4 acc = make_float4(0.f, 0.f, 0.f, 0.f);
    float4 den2 = make_float4(0.f, 0.f, 0.f, 0.f);
    float4 acc2 = make_float4(0.f, 0.f, 0.f, 0.f);

    int i = 0;
    for (; i + 2 <= deg; i += 2) {
        int s0 = ssrc[w][i];
        int s1 = ssrc[w][i + 1];
        float4 a = *(const float4*)(g_z + s0 * DD + lane * 4);
        float4 b = *(const float4*)(g_z + s1 * DD + lane * 4);
        float w0, w1;
        w0 = ex2(a.x * ze.x); den.x += w0; acc.x = fmaf(w0, a.x, acc.x);
        w1 = ex2(b.x * ze.x); den2.x += w1; acc2.x = fmaf(w1, b.x, acc2.x);
        w0 = ex2(a.y * ze.y); den.y += w0; acc.y = fmaf(w0, a.y, acc.y);
        w1 = ex2(b.y * ze.y); den2.y += w1; acc2.y = fmaf(w1, b.y, acc2.y);
        w0 = ex2(a.z * ze.z); den.z += w0; acc.z = fmaf(w0, a.z, acc.z);
        w1 = ex2(b.z * ze.z); den2.z += w1; acc2.z = fmaf(w1, b.z, acc2.z);
        w0 = ex2(a.w * ze.w); den.w += w0; acc.w = fmaf(w0, a.w, acc.w);
        w1 = ex2(b.w * ze.w); den2.w += w1; acc2.w = fmaf(w1, b.w, acc2.w);
    }
    if (i < deg) {
        int s0 = ssrc[w][i];
        float4 a = *(const float4*)(g_z + s0 * DD + lane * 4);
        float w0;
        w0 = ex2(a.x * ze.x); den.x += w0; acc.x = fmaf(w0, a.x, acc.x);
        w0 = ex2(a.y * ze.y); den.y += w0; acc.y = fmaf(w0, a.y, acc.y);
        w0 = ex2(a.z * ze.z); den.z += w0; acc.z = fmaf(w0, a.z, acc.z);
        w0 = ex2(a.w * ze.w); den.w += w0; acc.w = fmaf(w0, a.w, acc.w);
    }
    den.x += den2.x; den.y += den2.y; den.z += den2.z; den.w += den2.w;
    acc.x += acc2.x; acc.y += acc2.y; acc.z += acc2.z; acc.w += acc2.w;

    float sn = snorm[d];
    float4 hv;
    hv.x = (den.x > 0.f) ? (acc.x / den.x) * sn : 0.f;
    hv.y = (den.y > 0.f) ? (acc.y / den.y) * sn : 0.f;
    hv.z = (den.z > 0.f) ? (acc.z / den.z) * sn : 0.f;
    hv.w = (den.w > 0.f) ? (acc.w / den.w) * sn : 0.f;

    *(float4*)(g_hout + d * DD + lane * 4) = hv;
    *(float4*)(&shv[w][lane * 4]) = hv;
    __syncthreads();

    // BN partial stats: threads 0..127 sum channel c; 128..255 sumsq channel c-128
    int tid = threadIdx.x;
    int c = tid & (DD - 1);
    if (tid < DD) {
        float s = 0.f;
#pragma unroll
        for (int ww = 0; ww < WPB; ww++) s += shv[ww][c];
        atomicAdd(&g_stats[c], s);
    } else {
        float s2 = 0.f;
#pragma unroll
        for (int ww = 0; ww < WPB; ww++) { float v = shv[ww][c]; s2 = fmaf(v, v, s2); }
        atomicAdd(&g_stats[DD + c], s2);
    }
}

// ---------------- fold BN stats into scale/bias ----------------
__global__ void finalize_kernel(const float* __restrict__ gamma,
                                const float* __restrict__ beta) {
    int c = threadIdx.x;
    const float invN = 1.f / (float)NN;
    float mu = g_stats[c] * invN;
    float var = g_stats[DD + c] * invN - mu * mu;
    float sc = rsqrtf(var + 1e-5f) * gamma[c];
    g_scale[c] = sc;
    g_bias[c] = beta[c] - mu * sc;
}

// ---------------- BN apply + ELU ----------------
__global__ void apply_kernel(float* __restrict__ out) {
    int q = blockIdx.x * 256 + threadIdx.x;
    if (q >= NN * DD / 4) return;
    int c4 = q & 31;
    float4 hv = *(const float4*)&g_hout[q * 4];
    float4 sc = *(const float4*)&g_scale[c4 * 4];
    float4 bi = *(const float4*)&g_bias[c4 * 4];
    float4 o;
    float v;
    v = fmaf(hv.x, sc.x, bi.x); o.x = (v > 0.f) ? v : expm1f(v);
    v = fmaf(hv.y, sc.y, bi.y); o.y = (v > 0.f) ? v : expm1f(v);
    v = fmaf(hv.z, sc.z, bi.z); o.z = (v > 0.f) ? v : expm1f(v);
    v = fmaf(hv.w, sc.w, bi.w); o.w = (v > 0.f) ? v : expm1f(v);
    *(float4*)&out[q * 4] = o;
}

// ---------------- launch ----------------
extern "C" void kernel_launch(void* const* d_in, const int* in_sizes, int n_in,
                              void* d_out, int out_size) {
    const float* h      = (const float*)d_in[0];
    const float* snorm  = (const float*)d_in[1];
    const float* W      = (const float*)d_in[2];
    const float* gamma  = (const float*)d_in[3];
    const float* beta   = (const float*)d_in[4];
    const int*   src    = (const int*)d_in[5];
    const int*   dst    = (const int*)d_in[6];
    float* out = (float*)d_out;

    zero_kernel<<<(NN + 255) / 256, 256>>>();
    gemm_kernel<<<(NN + 63) / 64, 256>>>(h, W);
    build_kernel<<<(EE + 255) / 256, 256>>>(src, dst);
    agg_kernel<<<NN / WPB, 32 * WPB>>>(snorm);
    finalize_kernel<<<1, DD>>>(gamma, beta);
    apply_kernel<<<(NN * DD / 4 + 255) / 256, 256>>>(out);
}